// round 3
// baseline (speedup 1.0000x reference)
#include <cuda_runtime.h>
#include <cuda_bf16.h>
#include <math.h>

#define NN 100000          // nodes
#define NE 3200000         // edges
#define NG 512             // graphs
#define NF 128             // input features
#define BN_EPS 1e-5f

// ---------------- scratch (device globals; no allocations allowed) ----------
__device__ float g_y1[NN * 32];    // x @ W_rel1, padded 30->32 (128B rows)
__device__ float g_agg1[NN * 32];  // init = x @ W_root1 + b1; gather adds edges
__device__ float g_y2[NN * 20];    // h @ W_rel2
__device__ float g_agg2[NN * 20];  // init = h @ W_root2 + b2; gather adds edges
__device__ int   g_deg[NN];        // in-degree histogram
__device__ int   g_off[NN];        // CSR exclusive offsets
__device__ int   g_cur[NN];        // fill cursors
__device__ int   g_csr[NE];        // src node ids grouped by dst

// ---------------- helpers ----------------------------------------------------
// packed fp32x2 FMA (sm_100+)
__device__ __forceinline__ float2 ffma2(float2 a, float2 b, float2 c) {
    float2 d;
    asm("fma.rn.f32x2 %0, %1, %2, %3;"
        : "=l"(reinterpret_cast<unsigned long long&>(d))
        : "l"(reinterpret_cast<unsigned long long&>(a)),
          "l"(reinterpret_cast<unsigned long long&>(b)),
          "l"(reinterpret_cast<unsigned long long&>(c)));
    return d;
}

// ---------------- CSR construction -------------------------------------------
__global__ void k_zero_deg(int n) {
    int i = blockIdx.x * blockDim.x + threadIdx.x;
    if (i < n) g_deg[i] = 0;
}

__global__ void k_hist(const int* __restrict__ ei, int nE) {
    int e = blockIdx.x * blockDim.x + threadIdx.x;
    if (e >= nE) return;
    atomicAdd(&g_deg[__ldg(&ei[nE + e])], 1);   // result unused -> RED
}

// single-block exclusive scan of g_deg -> g_off, g_cur
__global__ void __launch_bounds__(1024) k_scan(int n) {
    __shared__ int ssum[1024];
    int t = threadIdx.x;
    int C = (n + 1023) >> 10;
    int lo = t * C;
    int hi = min(lo + C, n);
    int s = 0;
#pragma unroll 4
    for (int i = lo; i < hi; i++) s += g_deg[i];
    ssum[t] = s;
    __syncthreads();
    // Hillis-Steele inclusive scan
    for (int off = 1; off < 1024; off <<= 1) {
        int v = (t >= off) ? ssum[t - off] : 0;
        __syncthreads();
        ssum[t] += v;
        __syncthreads();
    }
    int run = ssum[t] - s;   // exclusive prefix for this chunk
#pragma unroll 4
    for (int i = lo; i < hi; i++) {
        g_off[i] = run;
        g_cur[i] = run;
        run += g_deg[i];
    }
}

__global__ void k_fill(const int* __restrict__ ei, int nE) {
    int e = blockIdx.x * blockDim.x + threadIdx.x;
    if (e >= nE) return;
    int s = __ldg(&ei[e]);
    int d = __ldg(&ei[nE + e]);
    int pos = atomicAdd(&g_cur[d], 1);
    g_csr[pos] = s;
}

// ---------------- kernel: node transform 1 (128 -> 30 rel + 30 root) --------
__global__ void __launch_bounds__(128) k_node1(
    const float* __restrict__ x,
    const float* __restrict__ Wrel,   // [128,30]
    const float* __restrict__ Wroot,  // [128,30]
    const float* __restrict__ b1,     // [30]
    int n)
{
    __shared__ float Ws[128 * 60];
    __shared__ float bs[30];
    for (int i = threadIdx.x; i < 128 * 30; i += 128) {
        int k = i / 30, j = i % 30;
        Ws[k * 60 + j]      = Wrel[i];
        Ws[k * 60 + 30 + j] = Wroot[i];
    }
    if (threadIdx.x < 30) bs[threadIdx.x] = b1[threadIdx.x];
    __syncthreads();

    int node = blockIdx.x * 128 + threadIdx.x;
    if (node >= n) return;

    float2 acc[30];
#pragma unroll
    for (int p = 0; p < 30; p++) acc[p] = make_float2(0.f, 0.f);

    const float4* xr = reinterpret_cast<const float4*>(x) + node * 32;
#pragma unroll 4
    for (int k4 = 0; k4 < 32; k4++) {
        float4 xv = __ldg(xr + k4);
#pragma unroll
        for (int q = 0; q < 4; q++) {
            float xs = (q == 0) ? xv.x : (q == 1) ? xv.y : (q == 2) ? xv.z : xv.w;
            float2 xb = make_float2(xs, xs);
            const float4* w4 = reinterpret_cast<const float4*>(&Ws[(k4 * 4 + q) * 60]);
#pragma unroll
            for (int j4 = 0; j4 < 15; j4++) {
                float4 wv = w4[j4];
                acc[j4 * 2]     = ffma2(make_float2(wv.x, wv.y), xb, acc[j4 * 2]);
                acc[j4 * 2 + 1] = ffma2(make_float2(wv.z, wv.w), xb, acc[j4 * 2 + 1]);
            }
        }
    }

    float4* y = reinterpret_cast<float4*>(g_y1 + node * 32);
#pragma unroll
    for (int j4 = 0; j4 < 7; j4++)
        y[j4] = make_float4(acc[j4*2].x, acc[j4*2].y, acc[j4*2+1].x, acc[j4*2+1].y);
    y[7] = make_float4(acc[14].x, acc[14].y, 0.f, 0.f);

    float4* a = reinterpret_cast<float4*>(g_agg1 + node * 32);
#pragma unroll
    for (int j4 = 0; j4 < 7; j4++) {
        float2 p0 = acc[15 + j4*2], p1 = acc[16 + j4*2];
        a[j4] = make_float4(p0.x + bs[j4*4], p0.y + bs[j4*4+1],
                            p1.x + bs[j4*4+2], p1.y + bs[j4*4+3]);
    }
    a[7] = make_float4(acc[29].x + bs[28], acc[29].y + bs[29], 0.f, 0.f);
}

// ---------------- kernel: gather layer 1 (warp/node, 4 slots x 8 chunks) -----
__global__ void __launch_bounds__(256) k_gather1(int n) {
    int wid = threadIdx.x >> 5, lane = threadIdx.x & 31;
    int node = blockIdx.x * 8 + wid;
    if (node >= n) return;
    int slot = lane >> 3, chunk = lane & 7;
    int start = __ldg(&g_off[node]);
    int deg   = __ldg(&g_deg[node]);

    float4 acc = make_float4(0.f, 0.f, 0.f, 0.f);
    for (int i = slot; i < deg; i += 4) {
        int s = __ldg(&g_csr[start + i]);
        float4 v = __ldg(reinterpret_cast<const float4*>(g_y1) + s * 8 + chunk);
        acc.x += v.x; acc.y += v.y; acc.z += v.z; acc.w += v.w;
    }
#pragma unroll
    for (int off = 8; off <= 16; off <<= 1) {
        acc.x += __shfl_xor_sync(0xffffffffu, acc.x, off);
        acc.y += __shfl_xor_sync(0xffffffffu, acc.y, off);
        acc.z += __shfl_xor_sync(0xffffffffu, acc.z, off);
        acc.w += __shfl_xor_sync(0xffffffffu, acc.w, off);
    }
    if (slot == 0) {
        float4* p = reinterpret_cast<float4*>(g_agg1) + node * 8 + chunk;
        float4 r = *p;
        r.x += acc.x; r.y += acc.y; r.z += acc.z; r.w += acc.w;
        *p = r;
    }
}

// ---------------- kernel: node transform 2 -----------------------------------
__global__ void __launch_bounds__(128) k_node2(
    const float* __restrict__ bn1_g, const float* __restrict__ bn1_b,
    const float* __restrict__ bn1_m, const float* __restrict__ bn1_v,
    const float* __restrict__ Wrel2,   // [30,20]
    const float* __restrict__ Wroot2,  // [30,20]
    const float* __restrict__ b2,      // [20]
    int n)
{
    __shared__ float Ws[30 * 40];
    __shared__ float sc1[30], sh1[30], bs2[20];
    for (int i = threadIdx.x; i < 30 * 20; i += 128) {
        int k = i / 20, j = i % 20;
        Ws[k * 40 + j]      = Wrel2[i];
        Ws[k * 40 + 20 + j] = Wroot2[i];
    }
    if (threadIdx.x < 30) {
        float sc = bn1_g[threadIdx.x] * rsqrtf(bn1_v[threadIdx.x] + BN_EPS);
        sc1[threadIdx.x] = sc;
        sh1[threadIdx.x] = bn1_b[threadIdx.x] - bn1_m[threadIdx.x] * sc;
    }
    if (threadIdx.x < 20) bs2[threadIdx.x] = b2[threadIdx.x];
    __syncthreads();

    int node = blockIdx.x * 128 + threadIdx.x;
    if (node >= n) return;

    float av[32];
    const float4* ar = reinterpret_cast<const float4*>(g_agg1 + node * 32);
#pragma unroll
    for (int k4 = 0; k4 < 8; k4++) {
        float4 v = __ldg(ar + k4);
        av[k4*4+0] = v.x; av[k4*4+1] = v.y; av[k4*4+2] = v.z; av[k4*4+3] = v.w;
    }
    float h[30];
#pragma unroll
    for (int k = 0; k < 30; k++)
        h[k] = fmaxf(av[k], 0.f) * sc1[k] + sh1[k];

    float2 acc[20];
#pragma unroll
    for (int p = 0; p < 20; p++) acc[p] = make_float2(0.f, 0.f);

#pragma unroll
    for (int k = 0; k < 30; k++) {
        float2 xb = make_float2(h[k], h[k]);
        const float4* w4 = reinterpret_cast<const float4*>(&Ws[k * 40]);
#pragma unroll
        for (int j4 = 0; j4 < 10; j4++) {
            float4 wv = w4[j4];
            acc[j4 * 2]     = ffma2(make_float2(wv.x, wv.y), xb, acc[j4 * 2]);
            acc[j4 * 2 + 1] = ffma2(make_float2(wv.z, wv.w), xb, acc[j4 * 2 + 1]);
        }
    }

    float4* y = reinterpret_cast<float4*>(g_y2 + node * 20);
#pragma unroll
    for (int j4 = 0; j4 < 5; j4++)
        y[j4] = make_float4(acc[j4*2].x, acc[j4*2].y, acc[j4*2+1].x, acc[j4*2+1].y);

    float4* a = reinterpret_cast<float4*>(g_agg2 + node * 20);
#pragma unroll
    for (int j4 = 0; j4 < 5; j4++) {
        float2 p0 = acc[10 + j4*2], p1 = acc[11 + j4*2];
        a[j4] = make_float4(p0.x + bs2[j4*4], p0.y + bs2[j4*4+1],
                            p1.x + bs2[j4*4+2], p1.y + bs2[j4*4+3]);
    }
}

// ---------------- kernel: gather layer 2 (warp/node, 4 slots x 5 chunks) -----
__global__ void __launch_bounds__(256) k_gather2(int n) {
    int wid = threadIdx.x >> 5, lane = threadIdx.x & 31;
    int node = blockIdx.x * 8 + wid;
    if (node >= n) return;
    int slot = lane >> 3, chunk = lane & 7;
    bool act = chunk < 5;
    int start = __ldg(&g_off[node]);
    int deg   = __ldg(&g_deg[node]);

    float4 acc = make_float4(0.f, 0.f, 0.f, 0.f);
    for (int i = slot; i < deg; i += 4) {
        int s = __ldg(&g_csr[start + i]);
        if (act) {
            float4 v = __ldg(reinterpret_cast<const float4*>(g_y2) + s * 5 + chunk);
            acc.x += v.x; acc.y += v.y; acc.z += v.z; acc.w += v.w;
        }
    }
#pragma unroll
    for (int off = 8; off <= 16; off <<= 1) {
        acc.x += __shfl_xor_sync(0xffffffffu, acc.x, off);
        acc.y += __shfl_xor_sync(0xffffffffu, acc.y, off);
        acc.z += __shfl_xor_sync(0xffffffffu, acc.z, off);
        acc.w += __shfl_xor_sync(0xffffffffu, acc.w, off);
    }
    if (slot == 0 && act) {
        float4* p = reinterpret_cast<float4*>(g_agg2) + node * 5 + chunk;
        float4 r = *p;
        r.x += acc.x; r.y += acc.y; r.z += acc.z; r.w += acc.w;
        *p = r;
    }
}

// ---------------- kernel: per-graph pooling + MLP head -----------------------
__global__ void __launch_bounds__(32) k_pool_head(
    const int* __restrict__ batch, int n,
    const float* __restrict__ bn2_g, const float* __restrict__ bn2_b,
    const float* __restrict__ bn2_m, const float* __restrict__ bn2_v,
    const float* __restrict__ W1,    // [40,10]
    const float* __restrict__ bl1,   // [10]
    const float* __restrict__ W2,    // [10,1]
    const float* __restrict__ bl2,   // [1]
    float* __restrict__ out)
{
    int g = blockIdx.x;
    int lane = threadIdx.x;

    int lo = 0, hi = n;
    while (lo < hi) { int mid = (lo + hi) >> 1; if (__ldg(&batch[mid]) < g) lo = mid + 1; else hi = mid; }
    int start = lo;
    lo = start; hi = n;
    while (lo < hi) { int mid = (lo + hi) >> 1; if (__ldg(&batch[mid]) < g + 1) lo = mid + 1; else hi = mid; }
    int end = lo;
    int cnt = end - start;

    float sc = 0.f, sh = 0.f;
    if (lane < 20) {
        sc = __ldg(&bn2_g[lane]) * rsqrtf(__ldg(&bn2_v[lane]) + BN_EPS);
        sh = __ldg(&bn2_b[lane]) - __ldg(&bn2_m[lane]) * sc;
    }

    float sum = 0.f, mx = -INFINITY;
    if (lane < 20) {
        for (int nd = start; nd < end; nd++) {
            float a = __ldg(&g_agg2[nd * 20 + lane]);
            float v = fmaxf(a, 0.f) * sc + sh;
            sum += v;
            mx = fmaxf(mx, v);
        }
    }
    float mean = (lane < 20) ? (sum / fmaxf((float)cnt, 1.f)) : 0.f;
    if (cnt == 0 || lane >= 20) mx = 0.f;

    float o = 0.f;
#pragma unroll
    for (int j = 0; j < 10; j++) {
        float p = 0.f;
        if (lane < 20)
            p = mx * __ldg(&W1[lane * 10 + j]) + mean * __ldg(&W1[(lane + 20) * 10 + j]);
#pragma unroll
        for (int off = 16; off > 0; off >>= 1)
            p += __shfl_xor_sync(0xffffffffu, p, off);
        float z = fmaxf(p + __ldg(&bl1[j]), 0.f);
        o += z * __ldg(&W2[j]);
    }
    o += __ldg(&bl2[0]);
    float sig = 1.f / (1.f + expf(-o));
    if (lane == 0) out[g] = sig;
}

// ---------------- launch -----------------------------------------------------
extern "C" void kernel_launch(void* const* d_in, const int* in_sizes, int n_in,
                              void* d_out, int out_size) {
    const float* x      = (const float*)d_in[0];
    const int*   ei     = (const int*)  d_in[1];
    const int*   batch  = (const int*)  d_in[2];
    const float* Wrel1  = (const float*)d_in[3];
    const float* Wroot1 = (const float*)d_in[4];
    const float* b1     = (const float*)d_in[5];
    const float* bn1_g  = (const float*)d_in[6];
    const float* bn1_b  = (const float*)d_in[7];
    const float* bn1_m  = (const float*)d_in[8];
    const float* bn1_v  = (const float*)d_in[9];
    const float* Wrel2  = (const float*)d_in[10];
    const float* Wroot2 = (const float*)d_in[11];
    const float* b2     = (const float*)d_in[12];
    const float* bn2_g  = (const float*)d_in[13];
    const float* bn2_b  = (const float*)d_in[14];
    const float* bn2_m  = (const float*)d_in[15];
    const float* bn2_v  = (const float*)d_in[16];
    const float* W1     = (const float*)d_in[17];
    const float* bl1    = (const float*)d_in[18];
    const float* W2     = (const float*)d_in[19];
    const float* bl2    = (const float*)d_in[20];
    float* out = (float*)d_out;

    int n  = in_sizes[0] / NF;   // nodes
    int nE = in_sizes[1] / 2;    // edges

    // CSR build (by destination)
    k_zero_deg<<<(n + 255) / 256, 256>>>(n);
    k_hist<<<(nE + 255) / 256, 256>>>(ei, nE);
    k_scan<<<1, 1024>>>(n);
    k_fill<<<(nE + 255) / 256, 256>>>(ei, nE);

    // layer 1
    k_node1<<<(n + 127) / 128, 128>>>(x, Wrel1, Wroot1, b1, n);
    k_gather1<<<(n + 7) / 8, 256>>>(n);

    // layer 2
    k_node2<<<(n + 127) / 128, 128>>>(bn1_g, bn1_b, bn1_m, bn1_v,
                                      Wrel2, Wroot2, b2, n);
    k_gather2<<<(n + 7) / 8, 256>>>(n);

    // pooling + head
    k_pool_head<<<NG, 32>>>(batch, n, bn2_g, bn2_b, bn2_m, bn2_v,
                            W1, bl1, W2, bl2, out);
}

// round 4
// speedup vs baseline: 1.5211x; 1.5211x over previous
#include <cuda_runtime.h>
#include <cuda_bf16.h>
#include <math.h>

#define NN 100000          // nodes
#define NE 3200000         // edges
#define NG 512             // graphs
#define NF 128             // input features
#define BN_EPS 1e-5f

// ---------------- scratch (device globals; no allocations allowed) ----------
__device__ float g_y1[NN * 32];    // x @ W_rel1, padded 30->32 (128B rows)
__device__ float g_agg1[NN * 32];  // init = x @ W_root1 + b1; scatter adds edges
__device__ float g_y2[NN * 20];    // h @ W_rel2'
__device__ float g_agg2[NN * 20];  // init = h @ W_root2' + b2'; scatter adds edges

// ---------------- helpers ----------------------------------------------------
__device__ __forceinline__ void red_add_v4(float* p, float4 v) {
    asm volatile("red.global.add.v4.f32 [%0], {%1, %2, %3, %4};"
                 :: "l"(__cvta_generic_to_global(p)),
                    "f"(v.x), "f"(v.y), "f"(v.z), "f"(v.w)
                 : "memory");
}

// ---------------- kernel 1: node transform 1 (128 -> 30 rel + 30 root) ------
// g_y1 = x @ W_rel1 (pad 32) ; g_agg1 = x @ W_root1 + b1 (pad 32)
__global__ void __launch_bounds__(128) k_node1(
    const float* __restrict__ x,
    const float* __restrict__ Wrel,   // [128,30]
    const float* __restrict__ Wroot,  // [128,30]
    const float* __restrict__ b1,     // [30]
    int n)
{
    __shared__ float Ws[128 * 60];    // row k: [rel 30 | root 30], 240B rows (16B-aligned)
    __shared__ float bs[30];
    for (int i = threadIdx.x; i < 128 * 30; i += 128) {
        int k = i / 30, j = i % 30;
        Ws[k * 60 + j]      = Wrel[i];
        Ws[k * 60 + 30 + j] = Wroot[i];
    }
    if (threadIdx.x < 30) bs[threadIdx.x] = b1[threadIdx.x];
    __syncthreads();

    int node = blockIdx.x * 128 + threadIdx.x;
    if (node >= n) return;

    float acc[60];
#pragma unroll
    for (int j = 0; j < 60; j++) acc[j] = 0.f;

    const float4* xr = reinterpret_cast<const float4*>(x) + node * 32;
#pragma unroll 2
    for (int k4 = 0; k4 < 32; k4++) {
        float4 xv = __ldg(xr + k4);
#pragma unroll
        for (int q = 0; q < 4; q++) {
            float xs = (q == 0) ? xv.x : (q == 1) ? xv.y : (q == 2) ? xv.z : xv.w;
            const float4* w4 = reinterpret_cast<const float4*>(&Ws[(k4 * 4 + q) * 60]);
#pragma unroll
            for (int j4 = 0; j4 < 15; j4++) {
                float4 wv = w4[j4];           // LDS.128 broadcast
                acc[j4*4+0] += xs * wv.x;
                acc[j4*4+1] += xs * wv.y;
                acc[j4*4+2] += xs * wv.z;
                acc[j4*4+3] += xs * wv.w;
            }
        }
    }

    // y1 = rel part (acc[0..29]); agg1 init = root part (acc[30..59]) + b1
    float4* y = reinterpret_cast<float4*>(g_y1 + node * 32);
#pragma unroll
    for (int j4 = 0; j4 < 7; j4++)
        y[j4] = make_float4(acc[j4*4+0], acc[j4*4+1], acc[j4*4+2], acc[j4*4+3]);
    y[7] = make_float4(acc[28], acc[29], 0.f, 0.f);

    float4* a = reinterpret_cast<float4*>(g_agg1 + node * 32);
#pragma unroll
    for (int j4 = 0; j4 < 7; j4++)
        a[j4] = make_float4(acc[30+j4*4+0] + bs[j4*4+0], acc[30+j4*4+1] + bs[j4*4+1],
                            acc[30+j4*4+2] + bs[j4*4+2], acc[30+j4*4+3] + bs[j4*4+3]);
    a[7] = make_float4(acc[58] + bs[28], acc[59] + bs[29], 0.f, 0.f);
}

// ---------------- kernel 2: edge scatter 1 (R1 layout: 8 chunk-threads/edge) -
__global__ void __launch_bounds__(256) k_scatter1(const int* __restrict__ ei, int nE)
{
    long long gtid = (long long)blockIdx.x * blockDim.x + threadIdx.x;
    if (gtid >= (long long)nE * 8) return;
    int e = (int)(gtid >> 3);
    int c = (int)(gtid & 7);
    int s = __ldg(&ei[e]);
    int d = __ldg(&ei[nE + e]);
    float4 v = __ldg(reinterpret_cast<const float4*>(g_y1) + s * 8 + c);
    red_add_v4(g_agg1 + d * 32 + c * 4, v);
}

// ---------------- kernel 3: node transform 2 (bn1 folded into weights) ------
// h' = relu(agg1); y2 = h' @ (sc1*W_rel2) + sh1@W_rel2 ; agg2-init likewise + b2
__global__ void __launch_bounds__(128) k_node2(
    const float* __restrict__ bn1_g, const float* __restrict__ bn1_b,
    const float* __restrict__ bn1_m, const float* __restrict__ bn1_v,
    const float* __restrict__ Wrel2,   // [30,20]
    const float* __restrict__ Wroot2,  // [30,20]
    const float* __restrict__ b2,      // [20]
    int n)
{
    __shared__ float Ws[30 * 40];     // row k: [rel 20 | root 20] scaled by sc1[k], 160B rows
    __shared__ float sc1[30], sh1[30];
    __shared__ float cr[20], cq[20];  // constant terms: sh1 @ Wrel2, sh1 @ Wroot2 + b2

    if (threadIdx.x < 30) {
        float sc = bn1_g[threadIdx.x] * rsqrtf(bn1_v[threadIdx.x] + BN_EPS);
        sc1[threadIdx.x] = sc;
        sh1[threadIdx.x] = bn1_b[threadIdx.x] - bn1_m[threadIdx.x] * sc;
    }
    __syncthreads();
    for (int i = threadIdx.x; i < 30 * 20; i += 128) {
        int k = i / 20, j = i % 20;
        Ws[k * 40 + j]      = sc1[k] * Wrel2[i];
        Ws[k * 40 + 20 + j] = sc1[k] * Wroot2[i];
    }
    if (threadIdx.x < 40) {
        int j = threadIdx.x % 20;
        float s = (threadIdx.x < 20) ? 0.f : b2[j];
        if (threadIdx.x < 20) {
            for (int k = 0; k < 30; k++) s += sh1[k] * Wrel2[k * 20 + j];
            cr[j] = s;
        } else {
            for (int k = 0; k < 30; k++) s += sh1[k] * Wroot2[k * 20 + j];
            cq[j] = s;
        }
    }
    __syncthreads();

    int node = blockIdx.x * 128 + threadIdx.x;
    if (node >= n) return;

    float h[30];
    {
        const float4* ar = reinterpret_cast<const float4*>(g_agg1 + node * 32);
#pragma unroll
        for (int k4 = 0; k4 < 8; k4++) {
            float4 v = __ldg(ar + k4);
            if (k4*4+0 < 30) h[k4*4+0] = fmaxf(v.x, 0.f);
            if (k4*4+1 < 30) h[k4*4+1] = fmaxf(v.y, 0.f);
            if (k4*4+2 < 30) h[k4*4+2] = fmaxf(v.z, 0.f);
            if (k4*4+3 < 30) h[k4*4+3] = fmaxf(v.w, 0.f);
        }
    }

    float acc[40];
#pragma unroll
    for (int j = 0; j < 20; j++) { acc[j] = cr[j]; acc[20 + j] = cq[j]; }

#pragma unroll
    for (int k = 0; k < 30; k++) {
        float hv = h[k];
        const float4* w4 = reinterpret_cast<const float4*>(&Ws[k * 40]);
#pragma unroll
        for (int j4 = 0; j4 < 10; j4++) {
            float4 wv = w4[j4];
            acc[j4*4+0] += hv * wv.x;
            acc[j4*4+1] += hv * wv.y;
            acc[j4*4+2] += hv * wv.z;
            acc[j4*4+3] += hv * wv.w;
        }
    }

    float4* y = reinterpret_cast<float4*>(g_y2 + node * 20);
#pragma unroll
    for (int j4 = 0; j4 < 5; j4++)
        y[j4] = make_float4(acc[j4*4+0], acc[j4*4+1], acc[j4*4+2], acc[j4*4+3]);

    float4* a = reinterpret_cast<float4*>(g_agg2 + node * 20);
#pragma unroll
    for (int j4 = 0; j4 < 5; j4++)
        a[j4] = make_float4(acc[20+j4*4+0], acc[20+j4*4+1], acc[20+j4*4+2], acc[20+j4*4+3]);
}

// ---------------- kernel 4: edge scatter 2 (R1 layout: 5 chunk-threads/edge) -
__global__ void __launch_bounds__(256) k_scatter2(const int* __restrict__ ei, int nE)
{
    long long gtid = (long long)blockIdx.x * blockDim.x + threadIdx.x;
    if (gtid >= (long long)nE * 5) return;
    unsigned int u = (unsigned int)gtid;
    unsigned int e = u / 5u;
    unsigned int c = u - e * 5u;
    int s = __ldg(&ei[e]);
    int d = __ldg(&ei[nE + e]);
    float4 v = __ldg(reinterpret_cast<const float4*>(g_y2) + s * 5 + c);
    red_add_v4(g_agg2 + d * 20 + c * 4, v);
}

// ---------------- kernel 5: per-graph pooling + MLP head ---------------------
__global__ void __launch_bounds__(32) k_pool_head(
    const int* __restrict__ batch, int n,
    const float* __restrict__ bn2_g, const float* __restrict__ bn2_b,
    const float* __restrict__ bn2_m, const float* __restrict__ bn2_v,
    const float* __restrict__ W1,    // [40,10]
    const float* __restrict__ bl1,   // [10]
    const float* __restrict__ W2,    // [10,1]
    const float* __restrict__ bl2,   // [1]
    float* __restrict__ out)
{
    int g = blockIdx.x;
    int lane = threadIdx.x;

    int lo = 0, hi = n;
    while (lo < hi) { int mid = (lo + hi) >> 1; if (__ldg(&batch[mid]) < g) lo = mid + 1; else hi = mid; }
    int start = lo;
    lo = start; hi = n;
    while (lo < hi) { int mid = (lo + hi) >> 1; if (__ldg(&batch[mid]) < g + 1) lo = mid + 1; else hi = mid; }
    int end = lo;
    int cnt = end - start;

    float sc = 0.f, sh = 0.f;
    if (lane < 20) {
        sc = __ldg(&bn2_g[lane]) * rsqrtf(__ldg(&bn2_v[lane]) + BN_EPS);
        sh = __ldg(&bn2_b[lane]) - __ldg(&bn2_m[lane]) * sc;
    }

    // 2-way ILP over nodes
    float sum0 = 0.f, sum1 = 0.f, mx0 = -INFINITY, mx1 = -INFINITY;
    if (lane < 20) {
        int nd = start;
        for (; nd + 1 < end; nd += 2) {
            float a0 = __ldg(&g_agg2[nd * 20 + lane]);
            float a1 = __ldg(&g_agg2[(nd + 1) * 20 + lane]);
            float v0 = fmaxf(a0, 0.f) * sc + sh;
            float v1 = fmaxf(a1, 0.f) * sc + sh;
            sum0 += v0; mx0 = fmaxf(mx0, v0);
            sum1 += v1; mx1 = fmaxf(mx1, v1);
        }
        if (nd < end) {
            float a0 = __ldg(&g_agg2[nd * 20 + lane]);
            float v0 = fmaxf(a0, 0.f) * sc + sh;
            sum0 += v0; mx0 = fmaxf(mx0, v0);
        }
    }
    float sum = sum0 + sum1;
    float mx = fmaxf(mx0, mx1);
    float mean = (lane < 20) ? (sum / fmaxf((float)cnt, 1.f)) : 0.f;
    if (cnt == 0 || lane >= 20) mx = 0.f;

    float o = 0.f;
#pragma unroll
    for (int j = 0; j < 10; j++) {
        float p = 0.f;
        if (lane < 20)
            p = mx * __ldg(&W1[lane * 10 + j]) + mean * __ldg(&W1[(lane + 20) * 10 + j]);
#pragma unroll
        for (int off = 16; off > 0; off >>= 1)
            p += __shfl_xor_sync(0xffffffffu, p, off);
        float z = fmaxf(p + __ldg(&bl1[j]), 0.f);
        o += z * __ldg(&W2[j]);
    }
    o += __ldg(&bl2[0]);
    float sig = 1.f / (1.f + expf(-o));
    if (lane == 0) out[g] = sig;
}

// ---------------- launch -----------------------------------------------------
extern "C" void kernel_launch(void* const* d_in, const int* in_sizes, int n_in,
                              void* d_out, int out_size) {
    const float* x      = (const float*)d_in[0];
    const int*   ei     = (const int*)  d_in[1];
    const int*   batch  = (const int*)  d_in[2];
    const float* Wrel1  = (const float*)d_in[3];
    const float* Wroot1 = (const float*)d_in[4];
    const float* b1     = (const float*)d_in[5];
    const float* bn1_g  = (const float*)d_in[6];
    const float* bn1_b  = (const float*)d_in[7];
    const float* bn1_m  = (const float*)d_in[8];
    const float* bn1_v  = (const float*)d_in[9];
    const float* Wrel2  = (const float*)d_in[10];
    const float* Wroot2 = (const float*)d_in[11];
    const float* b2     = (const float*)d_in[12];
    const float* bn2_g  = (const float*)d_in[13];
    const float* bn2_b  = (const float*)d_in[14];
    const float* bn2_m  = (const float*)d_in[15];
    const float* bn2_v  = (const float*)d_in[16];
    const float* W1     = (const float*)d_in[17];
    const float* bl1    = (const float*)d_in[18];
    const float* W2     = (const float*)d_in[19];
    const float* bl2    = (const float*)d_in[20];
    float* out = (float*)d_out;

    int n  = in_sizes[0] / NF;   // nodes
    int nE = in_sizes[1] / 2;    // edges

    k_node1<<<(n + 127) / 128, 128>>>(x, Wrel1, Wroot1, b1, n);
    {
        long long total = (long long)nE * 8;
        k_scatter1<<<(unsigned)((total + 255) / 256), 256>>>(ei, nE);
    }
    k_node2<<<(n + 127) / 128, 128>>>(bn1_g, bn1_b, bn1_m, bn1_v,
                                      Wrel2, Wroot2, b2, n);
    {
        long long total = (long long)nE * 5;
        k_scatter2<<<(unsigned)((total + 255) / 256), 256>>>(ei, nE);
    }
    k_pool_head<<<NG, 32>>>(batch, n, bn2_g, bn2_b, bn2_m, bn2_v,
                            W1, bl1, W2, bl2, out);
}